// round 6
// baseline (speedup 1.0000x reference)
#include <cuda_runtime.h>
#include <cstdint>
#include <math.h>

#define NROWS 4096
#define D     128
#define AWORD 16
#define INV_TAU (1.0f/0.07f)
#define PITCH 132             // smem tile pitch in floats (conflict-free)

// ---------------- static device scratch ----------------
__device__ float    g_Z[2 * NROWS * D];        // tf32-rounded normalized [z1n; z2n]
__device__ unsigned g_bits[NROWS * AWORD];     // packed labels
__device__ int      g_cnt[NROWS];              // label row sums (int)
__device__ unsigned g_pm[NROWS * (NROWS/32)];  // pos_label bitmask [4096][128 words]
__device__ float    g_se[NROWS], g_ps[NROWS], g_np[NROWS];

// ---------------- helpers ----------------
__device__ __forceinline__ uint32_t smem_u32(const void* p) {
    uint32_t a;
    asm("{ .reg .u64 t; cvta.to.shared.u64 t, %1; cvt.u32.u64 %0, t; }" : "=r"(a) : "l"(p));
    return a;
}
__device__ __forceinline__ void cpa16(uint32_t dst, const void* src) {
    asm volatile("cp.async.cg.shared.global [%0], [%1], 16;" :: "r"(dst), "l"(src));
}
#define CP_COMMIT() asm volatile("cp.async.commit_group;" ::: "memory")
#define CP_WAIT0()  asm volatile("cp.async.wait_group 0;" ::: "memory")

__device__ __forceinline__ void mma_tf32(float* d, const uint32_t* a, const uint32_t* b) {
    asm volatile(
        "mma.sync.aligned.m16n8k8.row.col.f32.tf32.tf32.f32 "
        "{%0,%1,%2,%3}, {%4,%5,%6,%7}, {%8,%9}, {%0,%1,%2,%3};"
        : "+f"(d[0]), "+f"(d[1]), "+f"(d[2]), "+f"(d[3])
        : "r"(a[0]), "r"(a[1]), "r"(a[2]), "r"(a[3]), "r"(b[0]), "r"(b[1]));
}

// ---------------- kernel 1: fused prep — L2-normalize+tf32 round / pack+zero ----------------
__global__ void kprep(const float* __restrict__ z1, const float* __restrict__ z2,
                      const int* __restrict__ labels) {
    const int tid  = threadIdx.x;
    const int wid  = tid >> 5;
    const int lane = tid & 31;

    if (blockIdx.x < 1024) {
        int r = blockIdx.x * 8 + wid;
        const float* src = (r < NROWS) ? (z1 + (size_t)r * D) : (z2 + (size_t)(r - NROWS) * D);
        float4 v = ((const float4*)src)[lane];
        float ss = v.x*v.x + v.y*v.y + v.z*v.z + v.w*v.w;
        #pragma unroll
        for (int o = 16; o; o >>= 1) ss += __shfl_xor_sync(0xffffffffu, ss, o);
        float inv = 1.0f / fmaxf(sqrtf(ss), 1e-12f);
        float o4[4] = {v.x*inv, v.y*inv, v.z*inv, v.w*inv};
        uint32_t t4[4];
        #pragma unroll
        for (int q = 0; q < 4; ++q)
            asm("cvt.rna.tf32.f32 %0, %1;" : "=r"(t4[q]) : "f"(o4[q]));
        ((uint4*)(g_Z + (size_t)r * D))[lane] = make_uint4(t4[0], t4[1], t4[2], t4[3]);
    } else {
        int b2 = blockIdx.x - 1024;
        int r  = b2 * 8 + wid;
        int gidx = b2 * 256 + tid;
        if (gidx < NROWS) { g_se[gidx] = 0.f; g_ps[gidx] = 0.f; g_np[gidx] = 0.f; }
        const int* lp = labels + (size_t)r * 512;
        int cnt = 0; unsigned myw = 0;
        #pragma unroll
        for (int w = 0; w < AWORD; ++w) {
            unsigned word = __ballot_sync(0xffffffffu, lp[w * 32 + lane] != 0);
            if (lane == w) myw = word;
            cnt += __popc(word);
        }
        if (lane < AWORD) g_bits[r * AWORD + lane] = myw;
        if (lane == 0)    g_cnt[r] = cnt;
    }
}

// ---------------- kernel 2: jaccard pos mask — integer test, triangular grid ----------------
__global__ void __launch_bounds__(128) kjacc() {
    int rem = blockIdx.x, jb = 0;
    while (rem >= 32 - jb) { rem -= 32 - jb; ++jb; }
    int ib = jb + rem;

    __shared__ unsigned sib[128 * AWORD];
    __shared__ int      sci[128];

    int tid  = threadIdx.x;
    int lane = tid & 31, wid = tid >> 5;

    uint4 jr4[4];
    #pragma unroll
    for (int q = 0; q < 4; ++q)
        jr4[q] = ((const uint4*)(g_bits + (size_t)(jb*128 + tid) * AWORD))[q];
    const unsigned* jr = (const unsigned*)jr4;
    int sj = g_cnt[jb*128 + tid];
    #pragma unroll
    for (int q = 0; q < 4; ++q)
        ((uint4*)sib)[q * 128 + tid] = ((const uint4*)(g_bits + (size_t)ib * 128 * AWORD))[q * 128 + tid];
    sci[tid] = g_cnt[ib*128 + tid];
    __syncthreads();

    unsigned myword = 0;
    unsigned tw[4];
    #pragma unroll 2
    for (int i0 = 0; i0 < 128; i0 += 2) {
        const unsigned* iwA = sib + i0 * AWORD;
        const unsigned* iwB = iwA + AWORD;
        int a0=0, a1=0, a2=0, a3=0, b0=0, b1=0, b2=0, b3=0;
        #pragma unroll
        for (int w = 0; w < 4; ++w) {
            a0 += __popc(jr[w]      & iwA[w]);
            a1 += __popc(jr[w + 4]  & iwA[w + 4]);
            a2 += __popc(jr[w + 8]  & iwA[w + 8]);
            a3 += __popc(jr[w + 12] & iwA[w + 12]);
            b0 += __popc(jr[w]      & iwB[w]);
            b1 += __popc(jr[w + 4]  & iwB[w + 4]);
            b2 += __popc(jr[w + 8]  & iwB[w + 8]);
            b3 += __popc(jr[w + 12] & iwB[w + 12]);
        }
        int iA = (a0 + a1) + (a2 + a3);
        int iB = (b0 + b1) + (b2 + b3);
        long long uA = (long long)(sj + sci[i0]     - iA);
        long long uB = (long long)(sj + sci[i0 + 1] - iB);
        bool posA = (iA > 0) && (((long long)iA << 26) >= 20132659LL * uA);
        bool posB = (iB > 0) && (((long long)iB << 26) >= 20132659LL * uB);
        myword |= (posA ? 1u : 0u) << (i0 & 31);
        myword |= (posB ? 1u : 0u) << ((i0 + 1) & 31);
        unsigned balA = __ballot_sync(0xffffffffu, posA);
        unsigned balB = __ballot_sync(0xffffffffu, posB);
        if ((i0 & 31) == lane)       tw[i0 >> 5] = balA;
        if (((i0 + 1) & 31) == lane) tw[i0 >> 5] = balB;
        if ((i0 & 31) == 30) {
            g_pm[(size_t)(jb*128 + tid) * 128 + ib*4 + (i0 >> 5)] = myword;
            myword = 0;
        }
    }
    if (ib != jb) {
        #pragma unroll
        for (int q = 0; q < 4; ++q)
            g_pm[(size_t)(ib*128 + q*32 + lane) * 128 + jb*4 + wid] = tw[q];
    }
}

// ---------------- kernel 3: pipelined mma.sync tf32 GEMM + interleaved epilogue ----------------
// 256 threads, 8 warps (4 m x 2 n), 32x64 warp tiles. 128 blocks = 4 per anchor tile.
// smem floats: As [0,16896), Bs0 [16896,33792), Bs1 [33792,50688), pm [50688,51712)
#define SM_A  0
#define SM_B0 16896
#define SM_B1 33792
#define SM_PM 50688
#define SMEM_FLOATS 51712

__device__ __forceinline__ void ld_tileA(uint32_t sb, int jb, int tid) {
    const float* Asrc = g_Z + (size_t)jb * 128 * D;
    #pragma unroll
    for (int it = 0; it < 16; ++it) {
        int idx = it * 256 + tid;
        int r = idx >> 5, k4 = idx & 31;
        cpa16(sb + (uint32_t)(r * PITCH + k4 * 4) * 4u, Asrc + r * 128 + k4 * 4);
    }
}
__device__ __forceinline__ void ld_tileB(uint32_t sb, int ct, int jb, int tid) {
    const float* Bsrc = g_Z + (size_t)ct * 128 * D;
    uint32_t bo = sb + ((ct & 1) ? SM_B1 : SM_B0) * 4u;
    #pragma unroll
    for (int it = 0; it < 16; ++it) {
        int idx = it * 256 + tid;
        int r = idx >> 5, k4 = idx & 31;
        cpa16(bo + (uint32_t)(r * PITCH + k4 * 4) * 4u, Bsrc + r * 128 + k4 * 4);
    }
    if (tid < 128)
        cpa16(sb + (SM_PM + (ct & 1) * 512) * 4u + tid * 16,
              g_pm + (size_t)(jb * 128 + tid) * 128 + ((ct & 31) << 2));
}

// epilogue of one shadow value (compile-time e)
#define EPI(e, C0) do {                                                          \
    const int _mf = (e) >> 5, _nf = ((e) >> 2) & 7;                              \
    const int _h  = ((e) >> 1) & 1, _q = (e) & 1;                                \
    const int _ai = _mf * 2 + _h;                                                \
    const int _jr = jb * 128 + wm * 32 + _mf * 16 + _h * 8 + g;                  \
    const int _cg = (C0) + wn * 64 + _nf * 8 + tg * 2 + _q;                      \
    float _s  = fmaf(sh[e], INV_TAU, -INV_TAU);                                  \
    float _ex = __expf(_s);                                                      \
    unsigned _w = pmprev[_ai * 2 + (_nf >> 2)];                                  \
    bool _pos = (((_w >> ((_nf & 3) * 8 + tg * 2 + _q)) & 1u) != 0u)             \
              | (_cg == _jr + NROWS);                                            \
    if (_cg != _jr) { se[_ai] += _ex; if (_pos) { ps[_ai] += _s; np[_ai] += 1.f; } } \
} while (0)

__global__ void __launch_bounds__(256, 1) kmain() {
    extern __shared__ float sm[];
    const int tid  = threadIdx.x;
    const int lane = tid & 31, wid = tid >> 5;
    const int wm   = wid >> 1, wn = wid & 1;      // 4 m-warps x 2 n-warps
    const int g    = lane >> 2, tg = lane & 3;

    const int jb  = blockIdx.x >> 2;              // anchor tile
    const int ct0 = (blockIdx.x & 3) * 16;        // 16 column tiles, same jb

    uint32_t sb = smem_u32(sm);

    ld_tileA(sb, jb, tid);
    ld_tileB(sb, ct0, jb, tid);
    CP_COMMIT(); CP_WAIT0();
    __syncthreads();

    float se[4] = {0,0,0,0}, ps[4] = {0,0,0,0}, np[4] = {0,0,0,0};
    float sh[64];
    unsigned pmprev[8], pmcur[8];
    bool hp = false;
    int  c0p = 0;

    for (int t = 0; t < 16; ++t) {
        const int ct = ct0 + t;

        // pm words for this tile -> registers (before prefetch clobbers parity buffer)
        {
            const unsigned* pmS = (const unsigned*)(sm + SM_PM) + (ct & 1) * 512;
            #pragma unroll
            for (int r4 = 0; r4 < 4; ++r4) {
                int rl = wm * 32 + r4 * 8 + g;
                uint2 w = *(const uint2*)(pmS + rl * 4 + wn * 2);
                pmcur[r4 * 2 + 0] = w.x; pmcur[r4 * 2 + 1] = w.y;
            }
        }
        if (t + 1 < 16) { ld_tileB(sb, ct + 1, jb, tid); CP_COMMIT(); }

        float d[2][8][4];
        #pragma unroll
        for (int mf = 0; mf < 2; ++mf)
            #pragma unroll
            for (int nf = 0; nf < 8; ++nf)
                #pragma unroll
                for (int q = 0; q < 4; ++q) d[mf][nf][q] = 0.0f;

        const float* Aw = sm + SM_A + (wm * 32) * PITCH;
        const float* Bw = sm + ((ct & 1) ? SM_B1 : SM_B0) + (wn * 64) * PITCH;

        #pragma unroll
        for (int ks = 0; ks < 16; ++ks) {
            const int k0 = ks * 8;
            uint32_t a[2][4];
            #pragma unroll
            for (int mf = 0; mf < 2; ++mf) {
                const float* Ar = Aw + (mf * 16 + g) * PITCH + k0 + tg;
                a[mf][0] = __float_as_uint(Ar[0]);
                a[mf][1] = __float_as_uint(Ar[8 * PITCH]);
                a[mf][2] = __float_as_uint(Ar[4]);
                a[mf][3] = __float_as_uint(Ar[8 * PITCH + 4]);
            }
            #pragma unroll
            for (int nf = 0; nf < 8; ++nf) {
                const float* Br = Bw + (nf * 8 + g) * PITCH + k0 + tg;
                uint32_t b[2] = { __float_as_uint(Br[0]), __float_as_uint(Br[4]) };
                mma_tf32(d[0][nf], a[0], b);
                mma_tf32(d[1][nf], a[1], b);
            }
            // interleaved epilogue slice of previous tile (4 values per k-step)
            if (hp) {
                EPI(ks * 4 + 0, c0p);
                EPI(ks * 4 + 1, c0p);
                EPI(ks * 4 + 2, c0p);
                EPI(ks * 4 + 3, c0p);
            }
        }

        // stash accumulators + pm for deferred epilogue
        #pragma unroll
        for (int mf = 0; mf < 2; ++mf)
            #pragma unroll
            for (int nf = 0; nf < 8; ++nf)
                #pragma unroll
                for (int q = 0; q < 4; ++q) sh[mf * 32 + nf * 4 + q] = d[mf][nf][q];
        #pragma unroll
        for (int q = 0; q < 8; ++q) pmprev[q] = pmcur[q];
        c0p = ct * 128;
        hp = true;

        CP_WAIT0();
        __syncthreads();
    }

    // drain last tile's epilogue
    #pragma unroll
    for (int e = 0; e < 64; ++e) EPI(e, c0p);

    // reduce over the 4 lanes sharing a row, atomic merge (4 blocks per jb)
    #pragma unroll
    for (int ai = 0; ai < 4; ++ai) {
        float a = se[ai], b = ps[ai], c = np[ai];
        a += __shfl_xor_sync(0xffffffffu, a, 1); a += __shfl_xor_sync(0xffffffffu, a, 2);
        b += __shfl_xor_sync(0xffffffffu, b, 1); b += __shfl_xor_sync(0xffffffffu, b, 2);
        c += __shfl_xor_sync(0xffffffffu, c, 1); c += __shfl_xor_sync(0xffffffffu, c, 2);
        if (tg == 0) {
            int row = jb * 128 + wm * 32 + (ai >> 1) * 16 + (ai & 1) * 8 + g;
            atomicAdd(&g_se[row], a);
            atomicAdd(&g_ps[row], b);
            atomicAdd(&g_np[row], c);
        }
    }
}

// ---------------- kernel 4: per-row loss + mean ----------------
__global__ void kfinal(float* __restrict__ out) {
    __shared__ float red[1024];
    int tid = threadIdx.x;
    float s = 0.0f;
    for (int i = tid; i < NROWS; i += 1024) {
        float npv = g_np[i];                 // >= 1 (aug column)
        s += -(g_ps[i] - npv * logf(g_se[i] + 1e-8f)) / npv;
    }
    red[tid] = s;
    __syncthreads();
    for (int o = 512; o; o >>= 1) {
        if (tid < o) red[tid] += red[tid + o];
        __syncthreads();
    }
    if (tid == 0) out[0] = red[0] / (float)NROWS;
}

// ---------------- launch ----------------
extern "C" void kernel_launch(void* const* d_in, const int* in_sizes, int n_in,
                              void* d_out, int out_size) {
    const float* z1     = (const float*)d_in[0];
    const float* z2     = (const float*)d_in[1];
    const int*   labels = (const int*)d_in[2];
    float* out = (float*)d_out;

    cudaFuncSetAttribute(kmain, cudaFuncAttributeMaxDynamicSharedMemorySize,
                         SMEM_FLOATS * 4);

    kprep<<<1536, 256>>>(z1, z2, labels);
    kjacc<<<528, 128>>>();
    kmain<<<128, 256, SMEM_FLOATS * 4>>>();
    kfinal<<<1, 1024>>>(out);
}

// round 7
// speedup vs baseline: 1.1952x; 1.1952x over previous
#include <cuda_runtime.h>
#include <cuda_bf16.h>
#include <cstdint>
#include <math.h>

#define NROWS 4096
#define D     128
#define AWORD 16
#define INV_TAU (1.0f/0.07f)
#define PB    68              // smem row pitch in u32 (64 data + 4 pad; 4g+tg bank-bijective)

// ---------------- static device scratch ----------------
__device__ __nv_bfloat16 g_Zh[2 * NROWS * D];  // bf16 normalized [z1n; z2n] (2 MB)
__device__ unsigned g_bits[NROWS * AWORD];
__device__ int      g_cnt[NROWS];
__device__ unsigned g_pm[NROWS * (NROWS/32)];
__device__ float    g_se[NROWS], g_ps[NROWS], g_np[NROWS];
__device__ unsigned g_done;

// ---------------- helpers ----------------
__device__ __forceinline__ uint32_t smem_u32(const void* p) {
    uint32_t a;
    asm("{ .reg .u64 t; cvta.to.shared.u64 t, %1; cvt.u32.u64 %0, t; }" : "=r"(a) : "l"(p));
    return a;
}
__device__ __forceinline__ void cpa16(uint32_t dst, const void* src) {
    asm volatile("cp.async.cg.shared.global [%0], [%1], 16;" :: "r"(dst), "l"(src));
}
#define CP_COMMIT() asm volatile("cp.async.commit_group;" ::: "memory")
#define CP_WAIT0()  asm volatile("cp.async.wait_group 0;" ::: "memory")

__device__ __forceinline__ void mma_bf16(float* d, const uint32_t* a, const uint32_t* b) {
    asm volatile(
        "mma.sync.aligned.m16n8k16.row.col.f32.bf16.bf16.f32 "
        "{%0,%1,%2,%3}, {%4,%5,%6,%7}, {%8,%9}, {%0,%1,%2,%3};"
        : "+f"(d[0]), "+f"(d[1]), "+f"(d[2]), "+f"(d[3])
        : "r"(a[0]), "r"(a[1]), "r"(a[2]), "r"(a[3]), "r"(b[0]), "r"(b[1]));
}

// ---------------- kernel 1: fused prep — normalize->bf16 / pack+zero ----------------
__global__ void kprep(const float* __restrict__ z1, const float* __restrict__ z2,
                      const int* __restrict__ labels) {
    const int tid  = threadIdx.x;
    const int wid  = tid >> 5;
    const int lane = tid & 31;
    if (blockIdx.x == 0 && tid == 0) g_done = 0;

    if (blockIdx.x < 1024) {
        int r = blockIdx.x * 8 + wid;
        const float* src = (r < NROWS) ? (z1 + (size_t)r * D) : (z2 + (size_t)(r - NROWS) * D);
        float4 v = ((const float4*)src)[lane];
        float ss = v.x*v.x + v.y*v.y + v.z*v.z + v.w*v.w;
        #pragma unroll
        for (int o = 16; o; o >>= 1) ss += __shfl_xor_sync(0xffffffffu, ss, o);
        float inv = 1.0f / fmaxf(sqrtf(ss), 1e-12f);
        __nv_bfloat162 p0 = __floats2bfloat162_rn(v.x*inv, v.y*inv);
        __nv_bfloat162 p1 = __floats2bfloat162_rn(v.z*inv, v.w*inv);
        uint2 o2 = make_uint2(*(uint32_t*)&p0, *(uint32_t*)&p1);
        ((uint2*)g_Zh)[(size_t)r * 32 + lane] = o2;
    } else {
        int b2 = blockIdx.x - 1024;
        int r  = b2 * 8 + wid;
        int gidx = b2 * 256 + tid;
        if (gidx < NROWS) { g_se[gidx] = 0.f; g_ps[gidx] = 0.f; g_np[gidx] = 0.f; }
        const int* lp = labels + (size_t)r * 512;
        int cnt = 0; unsigned myw = 0;
        #pragma unroll
        for (int w = 0; w < AWORD; ++w) {
            unsigned word = __ballot_sync(0xffffffffu, lp[w * 32 + lane] != 0);
            if (lane == w) myw = word;
            cnt += __popc(word);
        }
        if (lane < AWORD) g_bits[r * AWORD + lane] = myw;
        if (lane == 0)    g_cnt[r] = cnt;
    }
}

// ---------------- kernel 2: jaccard pos mask — integer test, triangular grid ----------------
__global__ void __launch_bounds__(128) kjacc() {
    int rem = blockIdx.x, jb = 0;
    while (rem >= 32 - jb) { rem -= 32 - jb; ++jb; }
    int ib = jb + rem;

    __shared__ unsigned sib[128 * AWORD];
    __shared__ int      sci[128];

    int tid  = threadIdx.x;
    int lane = tid & 31, wid = tid >> 5;

    uint4 jr4[4];
    #pragma unroll
    for (int q = 0; q < 4; ++q)
        jr4[q] = ((const uint4*)(g_bits + (size_t)(jb*128 + tid) * AWORD))[q];
    const unsigned* jr = (const unsigned*)jr4;
    int sj = g_cnt[jb*128 + tid];
    #pragma unroll
    for (int q = 0; q < 4; ++q)
        ((uint4*)sib)[q * 128 + tid] = ((const uint4*)(g_bits + (size_t)ib * 128 * AWORD))[q * 128 + tid];
    sci[tid] = g_cnt[ib*128 + tid];
    __syncthreads();

    unsigned myword = 0;
    unsigned tw[4];
    #pragma unroll 2
    for (int i0 = 0; i0 < 128; i0 += 2) {
        const unsigned* iwA = sib + i0 * AWORD;
        const unsigned* iwB = iwA + AWORD;
        int a0=0, a1=0, a2=0, a3=0, b0=0, b1=0, b2=0, b3=0;
        #pragma unroll
        for (int w = 0; w < 4; ++w) {
            a0 += __popc(jr[w]      & iwA[w]);
            a1 += __popc(jr[w + 4]  & iwA[w + 4]);
            a2 += __popc(jr[w + 8]  & iwA[w + 8]);
            a3 += __popc(jr[w + 12] & iwA[w + 12]);
            b0 += __popc(jr[w]      & iwB[w]);
            b1 += __popc(jr[w + 4]  & iwB[w + 4]);
            b2 += __popc(jr[w + 8]  & iwB[w + 8]);
            b3 += __popc(jr[w + 12] & iwB[w + 12]);
        }
        int iA = (a0 + a1) + (a2 + a3);
        int iB = (b0 + b1) + (b2 + b3);
        long long uA = (long long)(sj + sci[i0]     - iA);
        long long uB = (long long)(sj + sci[i0 + 1] - iB);
        bool posA = (iA > 0) && (((long long)iA << 26) >= 20132659LL * uA);
        bool posB = (iB > 0) && (((long long)iB << 26) >= 20132659LL * uB);
        myword |= (posA ? 1u : 0u) << (i0 & 31);
        myword |= (posB ? 1u : 0u) << ((i0 + 1) & 31);
        unsigned balA = __ballot_sync(0xffffffffu, posA);
        unsigned balB = __ballot_sync(0xffffffffu, posB);
        if ((i0 & 31) == lane)       tw[i0 >> 5] = balA;
        if (((i0 + 1) & 31) == lane) tw[i0 >> 5] = balB;
        if ((i0 & 31) == 30) {
            g_pm[(size_t)(jb*128 + tid) * 128 + ib*4 + (i0 >> 5)] = myword;
            myword = 0;
        }
    }
    if (ib != jb) {
        #pragma unroll
        for (int q = 0; q < 4; ++q)
            g_pm[(size_t)(ib*128 + q*32 + lane) * 128 + jb*4 + wid] = tw[q];
    }
}

// ---------------- kernel 3: bf16 mma GEMM + fused epilogue + fused final ----------------
// 256 threads, 8 warps (4m x 2n), warp tile 32x64. 128 blocks, 16 tiles each, jb fixed.
// smem u32: A [0,8704), B0 [8704,17408), B1 [17408,26112), pm [26112,27136)
#define SM_A  0
#define SM_B0 8704
#define SM_B1 17408
#define SM_PM 26112
#define SMEM_U32 27136

__device__ __forceinline__ void ld_tileA(uint32_t sb, int jb, int tid) {
    const uint32_t* Asrc = (const uint32_t*)g_Zh + (size_t)jb * 128 * 64;
    #pragma unroll
    for (int it = 0; it < 8; ++it) {
        int idx = it * 256 + tid;
        int r = idx >> 4, gr = idx & 15;
        cpa16(sb + (uint32_t)(r * PB + gr * 4) * 4u, Asrc + r * 64 + gr * 4);
    }
}
__device__ __forceinline__ void ld_tileB(uint32_t sb, int ct, int jb, int tid) {
    const uint32_t* Bsrc = (const uint32_t*)g_Zh + (size_t)ct * 128 * 64;
    uint32_t bo = sb + ((ct & 1) ? SM_B1 : SM_B0) * 4u;
    #pragma unroll
    for (int it = 0; it < 8; ++it) {
        int idx = it * 256 + tid;
        int r = idx >> 4, gr = idx & 15;
        cpa16(bo + (uint32_t)(r * PB + gr * 4) * 4u, Bsrc + r * 64 + gr * 4);
    }
    if (tid < 128)
        cpa16(sb + (SM_PM + (ct & 1) * 512) * 4u + tid * 16,
              g_pm + (size_t)(jb * 128 + tid) * 128 + ((ct & 31) << 2));
}

__global__ void __launch_bounds__(256, 1) kmain(float* __restrict__ out) {
    extern __shared__ uint32_t sm32[];
    const int tid  = threadIdx.x;
    const int lane = tid & 31, wid = tid >> 5;
    const int wm   = wid >> 1, wn = wid & 1;      // 4 m-warps x 2 n-warps
    const int g    = lane >> 2, tg = lane & 3;

    const int jb  = blockIdx.x >> 2;
    const int ct0 = (blockIdx.x & 3) * 16;

    uint32_t sb = smem_u32(sm32);

    ld_tileA(sb, jb, tid);
    ld_tileB(sb, ct0, jb, tid);
    CP_COMMIT(); CP_WAIT0();
    __syncthreads();

    float se[4] = {0,0,0,0}, ps[4] = {0,0,0,0}, np[4] = {0,0,0,0};

    for (int t = 0; t < 16; ++t) {
        const int ct = ct0 + t;
        if (t + 1 < 16) { ld_tileB(sb, ct + 1, jb, tid); CP_COMMIT(); }

        float d[2][8][4];
        #pragma unroll
        for (int mf = 0; mf < 2; ++mf)
            #pragma unroll
            for (int nf = 0; nf < 8; ++nf)
                #pragma unroll
                for (int q = 0; q < 4; ++q) d[mf][nf][q] = 0.0f;

        const uint32_t* Aw = sm32 + SM_A + (wm * 32) * PB;
        const uint32_t* Bw = sm32 + ((ct & 1) ? SM_B1 : SM_B0) + (wn * 64) * PB;

        #pragma unroll
        for (int ks = 0; ks < 8; ++ks) {
            const int k0 = ks * 8;
            uint32_t a[2][4];
            #pragma unroll
            for (int mf = 0; mf < 2; ++mf) {
                const uint32_t* Ar = Aw + (mf * 16 + g) * PB + k0 + tg;
                a[mf][0] = Ar[0];
                a[mf][1] = Ar[8 * PB];
                a[mf][2] = Ar[4];
                a[mf][3] = Ar[8 * PB + 4];
            }
            #pragma unroll
            for (int nf = 0; nf < 8; ++nf) {
                const uint32_t* Br = Bw + (nf * 8 + g) * PB + k0 + tg;
                uint32_t b[2] = { Br[0], Br[4] };
                mma_bf16(d[0][nf], a[0], b);
                mma_bf16(d[1][nf], a[1], b);
            }
        }

        // ---- fused epilogue ----
        const unsigned* pmS = sm32 + SM_PM + (ct & 1) * 512;
        const int c0 = ct * 128;
        #pragma unroll
        for (int mf = 0; mf < 2; ++mf) {
            #pragma unroll
            for (int h = 0; h < 2; ++h) {
                const int rl   = wm * 32 + mf * 16 + h * 8 + g;
                const int jr   = jb * 128 + rl;
                const int jaug = jr + NROWS;
                const int ai   = mf * 2 + h;
                float a_se = 0.f, a_ps = 0.f, a_np = 0.f;
                #pragma unroll
                for (int nf = 0; nf < 8; ++nf) {
                    const int cl = wn * 64 + nf * 8 + tg * 2;
                    const unsigned w = pmS[rl * 4 + (cl >> 5)];
                    #pragma unroll
                    for (int q = 0; q < 2; ++q) {
                        const int cg = c0 + cl + q;
                        float v = d[mf][nf][h * 2 + q];
                        float s = fmaf(v, INV_TAU, -INV_TAU);
                        float e = __expf(s);
                        bool pos = (((w >> ((cl + q) & 31)) & 1u) != 0u) | (cg == jaug);
                        if (cg != jr) {
                            a_se += e;
                            if (pos) { a_ps += s; a_np += 1.f; }
                        }
                    }
                }
                se[ai] += a_se; ps[ai] += a_ps; np[ai] += a_np;
            }
        }

        CP_WAIT0();
        __syncthreads();
    }

    // ---- flush accumulators (4 blocks per jb) ----
    #pragma unroll
    for (int ai = 0; ai < 4; ++ai) {
        float a = se[ai], b = ps[ai], c = np[ai];
        a += __shfl_xor_sync(0xffffffffu, a, 1); a += __shfl_xor_sync(0xffffffffu, a, 2);
        b += __shfl_xor_sync(0xffffffffu, b, 1); b += __shfl_xor_sync(0xffffffffu, b, 2);
        c += __shfl_xor_sync(0xffffffffu, c, 1); c += __shfl_xor_sync(0xffffffffu, c, 2);
        if (tg == 0) {
            int row = jb * 128 + wm * 32 + (ai >> 1) * 16 + (ai & 1) * 8 + g;
            atomicAdd(&g_se[row], a);
            atomicAdd(&g_ps[row], b);
            atomicAdd(&g_np[row], c);
        }
    }

    // ---- last block performs the final reduction (no spinning) ----
    __threadfence();
    __syncthreads();
    __shared__ unsigned ticket;
    if (tid == 0) ticket = atomicAdd(&g_done, 1u);
    __syncthreads();
    if (ticket == 127) {
        __shared__ float red[256];
        float s = 0.0f;
        for (int i = tid; i < NROWS; i += 256) {
            float npv = g_np[i];                 // >= 1 (aug column)
            s += -(g_ps[i] - npv * logf(g_se[i] + 1e-8f)) / npv;
        }
        red[tid] = s;
        __syncthreads();
        for (int o = 128; o; o >>= 1) {
            if (tid < o) red[tid] += red[tid + o];
            __syncthreads();
        }
        if (tid == 0) out[0] = red[0] / (float)NROWS;
    }
}

// ---------------- launch ----------------
extern "C" void kernel_launch(void* const* d_in, const int* in_sizes, int n_in,
                              void* d_out, int out_size) {
    const float* z1     = (const float*)d_in[0];
    const float* z2     = (const float*)d_in[1];
    const int*   labels = (const int*)d_in[2];
    float* out = (float*)d_out;

    cudaFuncSetAttribute(kmain, cudaFuncAttributeMaxDynamicSharedMemorySize,
                         SMEM_U32 * 4);

    kprep<<<1536, 256>>>(z1, z2, labels);
    kjacc<<<528, 128>>>();
    kmain<<<128, 256, SMEM_U32 * 4>>>(out);
}

// round 8
// speedup vs baseline: 1.2930x; 1.0818x over previous
#include <cuda_runtime.h>
#include <cuda_bf16.h>
#include <cstdint>
#include <math.h>

#define NROWS 4096
#define D     128
#define AWORD 16
#define INV_TAU (1.0f/0.07f)
#define C1 ( 20.6155281026f)   //  INV_TAU * log2(e)
#define C2 (-20.6155281026f)   // -INV_TAU * log2(e)
#define PB    68               // smem row pitch in u32 (conflict-free: 4g+tg)

// ---------------- static device scratch ----------------
__device__ __nv_bfloat16 g_Zh[2 * NROWS * D];
__device__ unsigned g_bits[NROWS * AWORD];
__device__ int      g_cnt[NROWS];
__device__ unsigned g_pm[NROWS * (NROWS/32)];
__device__ float    g_se[NROWS], g_pv[NROWS];
__device__ int      g_npi[NROWS];
__device__ unsigned g_done;

// ---------------- helpers ----------------
__device__ __forceinline__ uint32_t smem_u32(const void* p) {
    uint32_t a;
    asm("{ .reg .u64 t; cvta.to.shared.u64 t, %1; cvt.u32.u64 %0, t; }" : "=r"(a) : "l"(p));
    return a;
}
__device__ __forceinline__ void cpa16(uint32_t dst, const void* src) {
    asm volatile("cp.async.cg.shared.global [%0], [%1], 16;" :: "r"(dst), "l"(src));
}
#define CP_COMMIT() asm volatile("cp.async.commit_group;" ::: "memory")
#define CP_WAIT0()  asm volatile("cp.async.wait_group 0;" ::: "memory")

__device__ __forceinline__ float ex2(float x) {
    float r;
    asm("ex2.approx.f32 %0, %1;" : "=f"(r) : "f"(x));
    return r;
}
__device__ __forceinline__ void mma_bf16(float* d, const uint32_t* a, const uint32_t* b) {
    asm volatile(
        "mma.sync.aligned.m16n8k16.row.col.f32.bf16.bf16.f32 "
        "{%0,%1,%2,%3}, {%4,%5,%6,%7}, {%8,%9}, {%0,%1,%2,%3};"
        : "+f"(d[0]), "+f"(d[1]), "+f"(d[2]), "+f"(d[3])
        : "r"(a[0]), "r"(a[1]), "r"(a[2]), "r"(a[3]), "r"(b[0]), "r"(b[1]));
}

// ---------------- kernel 1: fused prep ----------------
__global__ void kprep(const float* __restrict__ z1, const float* __restrict__ z2,
                      const int* __restrict__ labels) {
    const int tid  = threadIdx.x;
    const int wid  = tid >> 5;
    const int lane = tid & 31;
    if (blockIdx.x == 0 && tid == 0) g_done = 0;

    if (blockIdx.x < 1024) {
        int r = blockIdx.x * 8 + wid;
        const float* src = (r < NROWS) ? (z1 + (size_t)r * D) : (z2 + (size_t)(r - NROWS) * D);
        float4 v = ((const float4*)src)[lane];
        float ss = v.x*v.x + v.y*v.y + v.z*v.z + v.w*v.w;
        #pragma unroll
        for (int o = 16; o; o >>= 1) ss += __shfl_xor_sync(0xffffffffu, ss, o);
        float inv = 1.0f / fmaxf(sqrtf(ss), 1e-12f);
        __nv_bfloat162 p0 = __floats2bfloat162_rn(v.x*inv, v.y*inv);
        __nv_bfloat162 p1 = __floats2bfloat162_rn(v.z*inv, v.w*inv);
        uint2 o2 = make_uint2(*(uint32_t*)&p0, *(uint32_t*)&p1);
        ((uint2*)g_Zh)[(size_t)r * 32 + lane] = o2;
    } else {
        int b2 = blockIdx.x - 1024;
        int r  = b2 * 8 + wid;
        int gidx = b2 * 256 + tid;
        if (gidx < NROWS) { g_se[gidx] = 0.f; g_pv[gidx] = 0.f; g_npi[gidx] = 0; }
        const int* lp = labels + (size_t)r * 512;
        int cnt = 0; unsigned myw = 0;
        #pragma unroll
        for (int w = 0; w < AWORD; ++w) {
            unsigned word = __ballot_sync(0xffffffffu, lp[w * 32 + lane] != 0);
            if (lane == w) myw = word;
            cnt += __popc(word);
        }
        if (lane < AWORD) g_bits[r * AWORD + lane] = myw;
        if (lane == 0)    g_cnt[r] = cnt;
    }
}

// ---------------- kernel 2: jaccard pos mask + row popcounts ----------------
__global__ void __launch_bounds__(128) kjacc() {
    int rem = blockIdx.x, jb = 0;
    while (rem >= 32 - jb) { rem -= 32 - jb; ++jb; }
    int ib = jb + rem;

    __shared__ unsigned sib[128 * AWORD];
    __shared__ int      sci[128];

    int tid  = threadIdx.x;
    int lane = tid & 31, wid = tid >> 5;

    uint4 jr4[4];
    #pragma unroll
    for (int q = 0; q < 4; ++q)
        jr4[q] = ((const uint4*)(g_bits + (size_t)(jb*128 + tid) * AWORD))[q];
    const unsigned* jr = (const unsigned*)jr4;
    int sj = g_cnt[jb*128 + tid];
    #pragma unroll
    for (int q = 0; q < 4; ++q)
        ((uint4*)sib)[q * 128 + tid] = ((const uint4*)(g_bits + (size_t)ib * 128 * AWORD))[q * 128 + tid];
    sci[tid] = g_cnt[ib*128 + tid];
    __syncthreads();

    unsigned myword = 0;
    unsigned tw[4];
    int pcmy = 0;
    #pragma unroll 2
    for (int i0 = 0; i0 < 128; i0 += 2) {
        const unsigned* iwA = sib + i0 * AWORD;
        const unsigned* iwB = iwA + AWORD;
        int a0=0, a1=0, a2=0, a3=0, b0=0, b1=0, b2=0, b3=0;
        #pragma unroll
        for (int w = 0; w < 4; ++w) {
            a0 += __popc(jr[w]      & iwA[w]);
            a1 += __popc(jr[w + 4]  & iwA[w + 4]);
            a2 += __popc(jr[w + 8]  & iwA[w + 8]);
            a3 += __popc(jr[w + 12] & iwA[w + 12]);
            b0 += __popc(jr[w]      & iwB[w]);
            b1 += __popc(jr[w + 4]  & iwB[w + 4]);
            b2 += __popc(jr[w + 8]  & iwB[w + 8]);
            b3 += __popc(jr[w + 12] & iwB[w + 12]);
        }
        int iA = (a0 + a1) + (a2 + a3);
        int iB = (b0 + b1) + (b2 + b3);
        long long uA = (long long)(sj + sci[i0]     - iA);
        long long uB = (long long)(sj + sci[i0 + 1] - iB);
        bool posA = (iA > 0) && (((long long)iA << 26) >= 20132659LL * uA);
        bool posB = (iB > 0) && (((long long)iB << 26) >= 20132659LL * uB);
        myword |= (posA ? 1u : 0u) << (i0 & 31);
        myword |= (posB ? 1u : 0u) << ((i0 + 1) & 31);
        unsigned balA = __ballot_sync(0xffffffffu, posA);
        unsigned balB = __ballot_sync(0xffffffffu, posB);
        if ((i0 & 31) == lane)       tw[i0 >> 5] = balA;
        if (((i0 + 1) & 31) == lane) tw[i0 >> 5] = balB;
        if ((i0 & 31) == 30) {
            g_pm[(size_t)(jb*128 + tid) * 128 + ib*4 + (i0 >> 5)] = myword;
            pcmy += __popc(myword);
            myword = 0;
        }
    }
    atomicAdd(&g_npi[jb*128 + tid], pcmy);
    if (ib != jb) {
        #pragma unroll
        for (int q = 0; q < 4; ++q) {
            g_pm[(size_t)(ib*128 + q*32 + lane) * 128 + jb*4 + wid] = tw[q];
            atomicAdd(&g_npi[ib*128 + q*32 + lane], __popc(tw[q]));
        }
    }
}

// ---------------- kernel 3: bf16 mma GEMM + fused epilogue + fused final ----------------
// 256 threads, 8 warps (4m x 2n). 256 blocks (2/SM), 8 tiles each, jb fixed.
#define SM_A  0
#define SM_B0 8704
#define SM_B1 17408
#define SM_PM 26112
#define SMEM_U32 27136

__device__ __forceinline__ void ld_tileA(uint32_t sb, int jb, int tid) {
    const uint32_t* Asrc = (const uint32_t*)g_Zh + (size_t)jb * 128 * 64;
    #pragma unroll
    for (int it = 0; it < 8; ++it) {
        int idx = it * 256 + tid;
        int r = idx >> 4, gr = idx & 15;
        cpa16(sb + (uint32_t)(r * PB + gr * 4) * 4u, Asrc + r * 64 + gr * 4);
    }
}
__device__ __forceinline__ void ld_tileB(uint32_t sb, int ct, int jb, int tid) {
    const uint32_t* Bsrc = (const uint32_t*)g_Zh + (size_t)ct * 128 * 64;
    uint32_t bo = sb + ((ct & 1) ? SM_B1 : SM_B0) * 4u;
    #pragma unroll
    for (int it = 0; it < 8; ++it) {
        int idx = it * 256 + tid;
        int r = idx >> 4, gr = idx & 15;
        cpa16(bo + (uint32_t)(r * PB + gr * 4) * 4u, Bsrc + r * 64 + gr * 4);
    }
    if (tid < 128)
        cpa16(sb + (SM_PM + (ct & 1) * 512) * 4u + tid * 16,
              g_pm + (size_t)(jb * 128 + tid) * 128 + ((ct & 31) << 2));
}

__global__ void __launch_bounds__(256, 2) kmain(float* __restrict__ out) {
    extern __shared__ uint32_t sm32[];
    const int tid  = threadIdx.x;
    const int lane = tid & 31, wid = tid >> 5;
    const int wm   = wid >> 1, wn = wid & 1;
    const int g    = lane >> 2, tg = lane & 3;

    const int jb  = blockIdx.x >> 3;
    const int ct0 = (blockIdx.x & 7) * 8;

    uint32_t sb = smem_u32(sm32);

    ld_tileA(sb, jb, tid);
    ld_tileB(sb, ct0, jb, tid);
    CP_COMMIT(); CP_WAIT0();
    __syncthreads();

    float se[4] = {0,0,0,0}, pv[4] = {0,0,0,0};

    for (int t = 0; t < 8; ++t) {
        const int ct = ct0 + t;
        if (t + 1 < 8) { ld_tileB(sb, ct + 1, jb, tid); CP_COMMIT(); }

        float d[2][8][4];
        #pragma unroll
        for (int mf = 0; mf < 2; ++mf)
            #pragma unroll
            for (int nf = 0; nf < 8; ++nf)
                #pragma unroll
                for (int q = 0; q < 4; ++q) d[mf][nf][q] = 0.0f;

        const uint32_t* Aw = sm32 + SM_A + (wm * 32) * PB;
        const uint32_t* Bw = sm32 + ((ct & 1) ? SM_B1 : SM_B0) + (wn * 64) * PB;

        #pragma unroll
        for (int ks = 0; ks < 8; ++ks) {
            const int k0 = ks * 8;
            uint32_t a[2][4];
            #pragma unroll
            for (int mf = 0; mf < 2; ++mf) {
                const uint32_t* Ar = Aw + (mf * 16 + g) * PB + k0 + tg;
                a[mf][0] = Ar[0];
                a[mf][1] = Ar[8 * PB];
                a[mf][2] = Ar[4];
                a[mf][3] = Ar[8 * PB + 4];
            }
            #pragma unroll
            for (int nf = 0; nf < 8; ++nf) {
                const uint32_t* Br = Bw + (nf * 8 + g) * PB + k0 + tg;
                uint32_t b[2] = { Br[0], Br[4] };
                mma_bf16(d[0][nf], a[0], b);
                mma_bf16(d[1][nf], a[1], b);
            }
        }

        // ---- fused epilogue: accumulate se (all, excl self) and pv (pos, excl self) ----
        const unsigned* pmS = sm32 + SM_PM + (ct & 1) * 512;
        const int c0 = ct * 128;
        #pragma unroll
        for (int mf = 0; mf < 2; ++mf) {
            #pragma unroll
            for (int h = 0; h < 2; ++h) {
                const int rl   = wm * 32 + mf * 16 + h * 8 + g;
                const int jr   = jb * 128 + rl;
                const int jaug = jr + NROWS;
                const int ai   = mf * 2 + h;
                float a_se = 0.f, a_pv = 0.f;
                #pragma unroll
                for (int nf = 0; nf < 8; ++nf) {
                    const int cl = wn * 64 + nf * 8 + tg * 2;
                    const unsigned w = pmS[rl * 4 + (cl >> 5)];
                    #pragma unroll
                    for (int q = 0; q < 2; ++q) {
                        const int cg = c0 + cl + q;
                        float v = d[mf][nf][h * 2 + q];
                        float e = ex2(fmaf(v, C1, C2));
                        bool pos = (((w >> ((cl + q) & 31)) & 1u) != 0u) | (cg == jaug);
                        if (cg != jr) {
                            a_se += e;
                            if (pos) a_pv += v;
                        }
                    }
                }
                se[ai] += a_se; pv[ai] += a_pv;
            }
        }

        CP_WAIT0();
        __syncthreads();
    }

    // ---- flush (8 blocks per jb) ----
    #pragma unroll
    for (int ai = 0; ai < 4; ++ai) {
        float a = se[ai], b = pv[ai];
        a += __shfl_xor_sync(0xffffffffu, a, 1); a += __shfl_xor_sync(0xffffffffu, a, 2);
        b += __shfl_xor_sync(0xffffffffu, b, 1); b += __shfl_xor_sync(0xffffffffu, b, 2);
        if (tg == 0) {
            int row = jb * 128 + wm * 32 + (ai >> 1) * 16 + (ai & 1) * 8 + g;
            atomicAdd(&g_se[row], a);
            atomicAdd(&g_pv[row], b);
        }
    }

    // ---- last block reduces ----
    __threadfence();
    __syncthreads();
    __shared__ unsigned ticket;
    if (tid == 0) ticket = atomicAdd(&g_done, 1u);
    __syncthreads();
    if (ticket == 255) {
        __shared__ float red[256];
        float s = 0.0f;
        for (int i = tid; i < NROWS; i += 256) {
            unsigned pmjj = (g_pm[(size_t)i * 128 + (i >> 5)] >> (i & 31)) & 1u;
            float np = (float)(2 * (g_npi[i] - (int)pmjj) + 1);   // >= 1
            float ps = INV_TAU * (g_pv[i] - np);
            s += -(ps - np * logf(g_se[i] + 1e-8f)) / np;
        }
        red[tid] = s;
        __syncthreads();
        for (int o = 128; o; o >>= 1) {
            if (tid < o) red[tid] += red[tid + o];
            __syncthreads();
        }
        if (tid == 0) out[0] = red[0] / (float)NROWS;
    }
}

// ---------------- launch ----------------
extern "C" void kernel_launch(void* const* d_in, const int* in_sizes, int n_in,
                              void* d_out, int out_size) {
    const float* z1     = (const float*)d_in[0];
    const float* z2     = (const float*)d_in[1];
    const int*   labels = (const int*)d_in[2];
    float* out = (float*)d_out;

    cudaFuncSetAttribute(kmain, cudaFuncAttributeMaxDynamicSharedMemorySize,
                         SMEM_U32 * 4);

    kprep<<<1536, 256>>>(z1, z2, labels);
    kjacc<<<528, 128>>>();
    kmain<<<256, 256, SMEM_U32 * 4>>>(out);
}